// round 3
// baseline (speedup 1.0000x reference)
#include <cuda_runtime.h>
#include <cuda_fp16.h>
#include <math.h>

#define N_NODES 100000
#define N_EDGES 1600000
#define F_IN    128
#define F_E     32
#define DH      128   // D*H
#define NH      4     // heads
#define FULLM   0xffffffffu

// -------- scratch (static device globals; no allocation allowed) --------
__device__ __half2 g_np_h[(size_t)N_NODES * 64];      // node_proj fp16, 25.6 MB
__device__ float g_ssrc[N_NODES * NH];
__device__ float g_v[NH * F_E];                       // folded W_edge @ a_edge
__device__ int g_cnt[N_NODES];
__device__ int g_rowptr[N_NODES + 1];
__device__ int g_head[N_NODES];
struct alignas(32) Rec { float4 p; int src; int pad0, pad1, pad2; };
__device__ Rec g_rec[N_EDGES];                        // 51.2 MB, sorted by dst

// -------- v[h][k] = sum_d W_edge[k, h*32+d] * a_edge[h][d] --------
__global__ void k_prep_v(const float* __restrict__ W_edge,
                         const float* __restrict__ AK) {
    int t = threadIdx.x;            // 128 threads
    int h = t >> 5, k = t & 31;
    float s = 0.f;
#pragma unroll
    for (int d = 0; d < 32; d++)
        s += W_edge[k * DH + h * 32 + d] * AK[h * 96 + 64 + d];
    g_v[h * 32 + k] = s;
}

// -------- zero dst histogram --------
__global__ void k_zero_cnt() {
    int i = blockIdx.x * blockDim.x + threadIdx.x;
    if (i < N_NODES) g_cnt[i] = 0;
}

// -------- histogram of dst --------
__global__ void __launch_bounds__(256) k_hist(const int* __restrict__ EI) {
    int e = blockIdx.x * 256 + threadIdx.x;
    int2 ei = reinterpret_cast<const int2*>(EI)[e];
    atomicAdd(&g_cnt[ei.y], 1);
}

// -------- single-block exclusive scan of g_cnt -> g_rowptr, g_head --------
__global__ void __launch_bounds__(1024) k_scan() {
    __shared__ int s[1024];
    const int CH = (N_NODES + 1023) / 1024;   // 98
    int t = threadIdx.x;
    int b = t * CH;
    int mysum = 0;
    for (int i = 0; i < CH; i++) {
        int idx = b + i;
        if (idx < N_NODES) mysum += g_cnt[idx];
    }
    s[t] = mysum;
    __syncthreads();
    for (int o = 1; o < 1024; o <<= 1) {
        int v = (t >= o) ? s[t - o] : 0;
        __syncthreads();
        s[t] += v;
        __syncthreads();
    }
    int running = s[t] - mysum;   // exclusive prefix
    for (int i = 0; i < CH; i++) {
        int idx = b + i;
        if (idx < N_NODES) {
            g_rowptr[idx] = running;
            g_head[idx] = running;
            running += g_cnt[idx];
        }
    }
    if (t == 0) g_rowptr[N_NODES] = s[1023];
}

// -------- node_proj = NF @ W_node (fp16 out) + fused s_src scores --------
__global__ void __launch_bounds__(256) k_node_gemm(const float* __restrict__ NF,
                                                   const float* __restrict__ W,
                                                   const float* __restrict__ AK) {
    __shared__ float As[64 * 129];
    int t = threadIdx.x;
    int row0 = blockIdx.x * 64;
#pragma unroll
    for (int i = 0; i < 32; i++) {
        int idx = i * 256 + t;
        int r = idx >> 7, k = idx & 127;
        int gr = row0 + r;
        As[r * 129 + k] = (gr < N_NODES) ? NF[(size_t)gr * F_IN + k] : 0.f;
    }
    __syncthreads();

    int tx = t & 31, ty = t >> 5;
    float acc[8][4];
#pragma unroll
    for (int i = 0; i < 8; i++)
#pragma unroll
        for (int j = 0; j < 4; j++) acc[i][j] = 0.f;

    const float4* W4 = reinterpret_cast<const float4*>(W);
#pragma unroll 4
    for (int k = 0; k < 128; k++) {
        float4 b = W4[k * 32 + tx];
#pragma unroll
        for (int i = 0; i < 8; i++) {
            float a = As[(ty * 8 + i) * 129 + k];
            acc[i][0] += a * b.x;
            acc[i][1] += a * b.y;
            acc[i][2] += a * b.z;
            acc[i][3] += a * b.w;
        }
    }

    // epilogue: fp16 store + fused s_src dot (s_dst cancels in segment softmax)
    int h = tx >> 3;
    int dl = (tx & 7) * 4;
    const float* a_s = AK + h * 96;
#pragma unroll
    for (int i = 0; i < 8; i++) {
        int gr = row0 + ty * 8 + i;
        if (gr < N_NODES) {
            __half2 h01 = __floats2half2_rn(acc[i][0], acc[i][1]);
            __half2 h23 = __floats2half2_rn(acc[i][2], acc[i][3]);
            uint2 raw;
            raw.x = *reinterpret_cast<unsigned*>(&h01);
            raw.y = *reinterpret_cast<unsigned*>(&h23);
            reinterpret_cast<uint2*>(g_np_h)[(size_t)gr * 32 + tx] = raw;
        }
        float ps = acc[i][0] * a_s[dl] + acc[i][1] * a_s[dl + 1]
                 + acc[i][2] * a_s[dl + 2] + acc[i][3] * a_s[dl + 3];
#pragma unroll
        for (int o = 4; o >= 1; o >>= 1)
            ps += __shfl_down_sync(FULLM, ps, o, 8);
        if ((tx & 7) == 0 && gr < N_NODES)
            g_ssrc[gr * 4 + h] = ps;
    }
}

// -------- permute pass: p = exp(s_src[src]+s_edge), counting-sort by dst ----
__global__ void __launch_bounds__(256) k_permute(const int* __restrict__ EI,
                                                 const float* __restrict__ EF) {
    __shared__ float sef[64 * 36];
    __shared__ float sv[128];
    __shared__ int2  sEI[64];
    __shared__ float sp[256];
    int t = threadIdx.x;
    int e0 = blockIdx.x * 64;
    if (t < 128) sv[t] = g_v[t];
    if (t < 64)  sEI[t] = reinterpret_cast<const int2*>(EI)[e0 + t];
#pragma unroll
    for (int i = 0; i < 2; i++) {
        int idx = i * 256 + t;
        int el = idx >> 3, c4 = idx & 7;
        float4 v = reinterpret_cast<const float4*>(EF + (size_t)(e0 + el) * F_E)[c4];
        *reinterpret_cast<float4*>(&sef[el * 36 + c4 * 4]) = v;
    }
    __syncthreads();

    {   // thread = (edge, head)
        int el = t >> 2, h = t & 3;
        int2 ei = sEI[el];
        const float* vh = sv + h * 32;
        float se = 0.f;
#pragma unroll
        for (int j = 0; j < 32; j++) se += sef[el * 36 + j] * vh[j];
        sp[t] = __expf(g_ssrc[ei.x * 4 + h] + se);
    }
    __syncthreads();

    if (t < 64) {
        int2 ei = sEI[t];
        int pos = atomicAdd(&g_head[ei.y], 1);
        float4 p4 = *reinterpret_cast<float4*>(&sp[t * 4]);
        g_rec[pos].p = p4;
        g_rec[pos].src = ei.x;
    }
}

// -------- fused gather-aggregate + softmax-normalize + W_out + gelu --------
__global__ void __launch_bounds__(256) k_agg_out(const float* __restrict__ Wo,
                                                 const float* __restrict__ bo,
                                                 float* __restrict__ out) {
    __shared__ float sW[128 * 32];
    __shared__ float sb[32];
    int t = threadIdx.x;
#pragma unroll
    for (int i = 0; i < 16; i++) sW[i * 256 + t] = Wo[i * 256 + t];
    if (t < 32) sb[t] = bo[t];
    __syncthreads();

    int lane = t & 31;
    int h = lane >> 3;
    const uint2* np2 = reinterpret_cast<const uint2*>(g_np_h);
    int gw = blockIdx.x * 8 + (t >> 5);
    const int stride = 1024 * 8;

    for (int n = gw; n < N_NODES; n += stride) {
        int beg = g_rowptr[n];
        int end = g_rowptr[n + 1];
        float acc[4] = {0.f, 0.f, 0.f, 0.f};
        float dsum = 0.f;

        for (int j0 = beg; j0 < end; j0 += 32) {
            int j = j0 + lane;
            float4 p4 = make_float4(0.f, 0.f, 0.f, 0.f);
            int srcL = 0;
            if (j < end) {
                p4 = g_rec[j].p;
                srcL = g_rec[j].src;
            }
            int m = min(32, end - j0);
            for (int q = 0; q < m; q++) {
                int src  = __shfl_sync(FULLM, srcL, q);
                float px = __shfl_sync(FULLM, p4.x, q);
                float py = __shfl_sync(FULLM, p4.y, q);
                float pz = __shfl_sync(FULLM, p4.z, q);
                float pw = __shfl_sync(FULLM, p4.w, q);
                float ph = (h & 2) ? ((h & 1) ? pw : pz) : ((h & 1) ? py : px);
                uint2 raw = np2[(size_t)src * 32 + lane];
                float2 f01 = __half22float2(*reinterpret_cast<__half2*>(&raw.x));
                float2 f23 = __half22float2(*reinterpret_cast<__half2*>(&raw.y));
                acc[0] += ph * f01.x;
                acc[1] += ph * f01.y;
                acc[2] += ph * f23.x;
                acc[3] += ph * f23.y;
                dsum += ph;
            }
        }

        float inv = 1.f / (dsum + 1e-8f);
        acc[0] *= inv; acc[1] *= inv; acc[2] *= inv; acc[3] *= inv;

        // in-warp matvec: out[col=lane] = sum_k A[k] * W[k][lane]
        float o = 0.f;
#pragma unroll
        for (int k = 0; k < 128; k++) {
            float a = __shfl_sync(FULLM, acc[k & 3], k >> 2);
            o += a * sW[k * 32 + lane];
        }
        float v = o + sb[lane];
        out[(size_t)n * 32 + lane] = 0.5f * v * (1.f + erff(v * 0.70710678118f));
    }
}

extern "C" void kernel_launch(void* const* d_in, const int* in_sizes, int n_in,
                              void* d_out, int out_size) {
    const float* NF = (const float*)d_in[0];   // node_features (N,128)
    const int*   EI = (const int*)  d_in[1];   // edge_index (E,2)
    const float* EF = (const float*)d_in[2];   // edge_features (E,32)
    const float* Wn = (const float*)d_in[3];   // W_node (128,128)
    const float* We = (const float*)d_in[4];   // W_edge (32,128)
    const float* AK = (const float*)d_in[5];   // attn_kernel (4,96)
    const float* Wo = (const float*)d_in[6];   // W_out (128,32)
    const float* bo = (const float*)d_in[7];   // b_out (32,)
    float* out = (float*)d_out;                // (N,32)

    k_prep_v<<<1, 128>>>(We, AK);
    k_zero_cnt<<<(N_NODES + 255) / 256, 256>>>();
    k_hist<<<N_EDGES / 256, 256>>>(EI);
    k_scan<<<1, 1024>>>();
    k_node_gemm<<<(N_NODES + 63) / 64, 256>>>(NF, Wn, AK);
    k_permute<<<N_EDGES / 64, 256>>>(EI, EF);
    k_agg_out<<<1024, 256>>>(Wo, bo, out);
}

// round 4
// speedup vs baseline: 1.4673x; 1.4673x over previous
#include <cuda_runtime.h>
#include <cuda_fp16.h>
#include <math.h>

#define N_NODES 100000
#define N_EDGES 1600000
#define F_IN    128
#define F_E     32
#define DH      128   // D*H
#define NH      4     // heads
#define FULLM   0xffffffffu
#define SCAN_BLOCKS 98   // ceil(100000/1024)

// -------- scratch (static device globals; no allocation allowed) --------
__device__ __half2 g_np_h[(size_t)N_NODES * 64];      // node_proj fp16, 25.6 MB
__device__ float g_ssrc[N_NODES * NH];
__device__ float g_v[NH * F_E];                       // folded W_edge @ a_edge
__device__ int g_cnt[N_NODES];
__device__ int g_rowptr[N_NODES + 1];
__device__ int g_head[N_NODES];
__device__ int g_part[128];
__device__ float4 g_p4[N_EDGES];                      // attn numerators, dst-sorted
__device__ int    g_src[N_EDGES];                     // src ids, dst-sorted

// -------- v[h][k] = sum_d W_edge[k, h*32+d] * a_edge[h][d] --------
__global__ void k_prep_v(const float* __restrict__ W_edge,
                         const float* __restrict__ AK) {
    int t = threadIdx.x;            // 128 threads
    int h = t >> 5, k = t & 31;
    float s = 0.f;
#pragma unroll
    for (int d = 0; d < 32; d++)
        s += W_edge[k * DH + h * 32 + d] * AK[h * 96 + 64 + d];
    g_v[h * 32 + k] = s;
}

__global__ void k_zero_cnt() {
    int i = blockIdx.x * blockDim.x + threadIdx.x;
    if (i < N_NODES) g_cnt[i] = 0;
}

__global__ void __launch_bounds__(256) k_hist(const int* __restrict__ EI) {
    int e = blockIdx.x * 256 + threadIdx.x;
    int2 ei = reinterpret_cast<const int2*>(EI)[e];
    atomicAdd(&g_cnt[ei.y], 1);
}

// -------- scan stage 1: per-block exclusive scan + block totals --------
__global__ void __launch_bounds__(1024) k_scan_blocks() {
    __shared__ int s[1024];
    int t = threadIdx.x;
    int i = blockIdx.x * 1024 + t;
    int v = (i < N_NODES) ? g_cnt[i] : 0;
    s[t] = v;
    __syncthreads();
    for (int o = 1; o < 1024; o <<= 1) {
        int u = (t >= o) ? s[t - o] : 0;
        __syncthreads();
        s[t] += u;
        __syncthreads();
    }
    if (i < N_NODES) g_rowptr[i] = s[t] - v;   // exclusive within block
    if (t == 1023) g_part[blockIdx.x] = s[1023];
}

// -------- scan stage 2: scan the 98 block totals --------
__global__ void k_scan_part() {
    __shared__ int s[128];
    int t = threadIdx.x;
    int v = (t < SCAN_BLOCKS) ? g_part[t] : 0;
    s[t] = v;
    __syncthreads();
    for (int o = 1; o < 128; o <<= 1) {
        int u = (t >= o) ? s[t - o] : 0;
        __syncthreads();
        s[t] += u;
        __syncthreads();
    }
    if (t < SCAN_BLOCKS) g_part[t] = s[t] - v;   // exclusive block offset
    if (t == 0) g_rowptr[N_NODES] = N_EDGES;
}

// -------- scan stage 3: add block offsets, init heads --------
__global__ void __launch_bounds__(1024) k_scan_add() {
    int i = blockIdx.x * 1024 + threadIdx.x;
    if (i < N_NODES) {
        int r = g_rowptr[i] + g_part[blockIdx.x];
        g_rowptr[i] = r;
        g_head[i] = r;
    }
}

// -------- node_proj = NF @ W_node (fp16 out) + fused s_src scores --------
__global__ void __launch_bounds__(256) k_node_gemm(const float* __restrict__ NF,
                                                   const float* __restrict__ W,
                                                   const float* __restrict__ AK) {
    __shared__ float As[64 * 129];
    int t = threadIdx.x;
    int row0 = blockIdx.x * 64;
#pragma unroll
    for (int i = 0; i < 32; i++) {
        int idx = i * 256 + t;
        int r = idx >> 7, k = idx & 127;
        int gr = row0 + r;
        As[r * 129 + k] = (gr < N_NODES) ? NF[(size_t)gr * F_IN + k] : 0.f;
    }
    __syncthreads();

    int tx = t & 31, ty = t >> 5;
    float acc[8][4];
#pragma unroll
    for (int i = 0; i < 8; i++)
#pragma unroll
        for (int j = 0; j < 4; j++) acc[i][j] = 0.f;

    const float4* W4 = reinterpret_cast<const float4*>(W);
#pragma unroll 4
    for (int k = 0; k < 128; k++) {
        float4 b = W4[k * 32 + tx];
#pragma unroll
        for (int i = 0; i < 8; i++) {
            float a = As[(ty * 8 + i) * 129 + k];
            acc[i][0] += a * b.x;
            acc[i][1] += a * b.y;
            acc[i][2] += a * b.z;
            acc[i][3] += a * b.w;
        }
    }

    // epilogue: fp16 store + fused s_src dot (s_dst cancels in segment softmax)
    int h = tx >> 3;
    int dl = (tx & 7) * 4;
    const float* a_s = AK + h * 96;
#pragma unroll
    for (int i = 0; i < 8; i++) {
        int gr = row0 + ty * 8 + i;
        if (gr < N_NODES) {
            __half2 h01 = __floats2half2_rn(acc[i][0], acc[i][1]);
            __half2 h23 = __floats2half2_rn(acc[i][2], acc[i][3]);
            uint2 raw;
            raw.x = *reinterpret_cast<unsigned*>(&h01);
            raw.y = *reinterpret_cast<unsigned*>(&h23);
            reinterpret_cast<uint2*>(g_np_h)[(size_t)gr * 32 + tx] = raw;
        }
        float ps = acc[i][0] * a_s[dl] + acc[i][1] * a_s[dl + 1]
                 + acc[i][2] * a_s[dl + 2] + acc[i][3] * a_s[dl + 3];
#pragma unroll
        for (int o = 4; o >= 1; o >>= 1)
            ps += __shfl_down_sync(FULLM, ps, o, 8);
        if ((tx & 7) == 0 && gr < N_NODES)
            g_ssrc[gr * 4 + h] = ps;
    }
}

// -------- permute pass: p = exp(s_src[src]+s_edge), counting-sort by dst ----
__global__ void __launch_bounds__(256) k_permute(const int* __restrict__ EI,
                                                 const float* __restrict__ EF) {
    __shared__ float sef[64 * 36];
    __shared__ float sv[128];
    __shared__ int2  sEI[64];
    __shared__ float sp[256];
    int t = threadIdx.x;
    int e0 = blockIdx.x * 64;
    if (t < 128) sv[t] = g_v[t];
    if (t < 64)  sEI[t] = reinterpret_cast<const int2*>(EI)[e0 + t];
#pragma unroll
    for (int i = 0; i < 2; i++) {
        int idx = i * 256 + t;
        int el = idx >> 3, c4 = idx & 7;
        float4 v = reinterpret_cast<const float4*>(EF + (size_t)(e0 + el) * F_E)[c4];
        *reinterpret_cast<float4*>(&sef[el * 36 + c4 * 4]) = v;
    }
    __syncthreads();

    {   // thread = (edge, head)
        int el = t >> 2, h = t & 3;
        int2 ei = sEI[el];
        const float* vh = sv + h * 32;
        float se = 0.f;
#pragma unroll
        for (int j = 0; j < 32; j++) se += sef[el * 36 + j] * vh[j];
        sp[t] = __expf(g_ssrc[ei.x * 4 + h] + se);
    }
    __syncthreads();

    if (t < 64) {
        int2 ei = sEI[t];
        int pos = atomicAdd(&g_head[ei.y], 1);
        g_p4[pos] = *reinterpret_cast<float4*>(&sp[t * 4]);
        g_src[pos] = ei.x;
    }
}

// -------- fused gather-aggregate + softmax-normalize + W_out + gelu --------
__global__ void __launch_bounds__(256) k_agg_out(const float* __restrict__ Wo,
                                                 const float* __restrict__ bo,
                                                 float* __restrict__ out) {
    __shared__ float sWt[32 * 132];   // W_out transposed [col][k], padded
    __shared__ float sb[32];
    __shared__ float s_p[8 * 128];    // per-warp staged attn numerators
    __shared__ int   s_src[8 * 32];   // per-warp staged src ids
    __shared__ float s_A[8 * 128];    // per-warp normalized agg vector
    int t = threadIdx.x, lane = t & 31, w = t >> 5;
    for (int idx = t; idx < 4096; idx += 256) {
        int k = idx >> 5, col = idx & 31;
        sWt[col * 132 + k] = Wo[idx];
    }
    if (t < 32) sb[t] = bo[t];
    __syncthreads();

    float* wp = s_p + w * 128;
    int* wsrc = s_src + w * 32;
    float* wA = s_A + w * 128;
    int h = lane >> 3;
    const uint2* np2 = reinterpret_cast<const uint2*>(g_np_h);

    for (int n = blockIdx.x * 8 + w; n < N_NODES; n += gridDim.x * 8) {
        int beg = g_rowptr[n];
        int end = g_rowptr[n + 1];
        float a0 = 0.f, a1 = 0.f, a2 = 0.f, a3 = 0.f, ds = 0.f;

        for (int j0 = beg; j0 < end; j0 += 32) {
            int j = j0 + lane;
            if (j < end) {
                *reinterpret_cast<float4*>(&wp[lane * 4]) = g_p4[j];
                wsrc[lane] = g_src[j];
            }
            __syncwarp();
            int m = min(32, end - j0);
#pragma unroll 4
            for (int q = 0; q < m; q++) {
                int src = wsrc[q];                 // LDS broadcast
                float ph = wp[q * 4 + h];          // LDS, 4 addrs/warp, CF
                uint2 raw = np2[(size_t)src * 32 + lane];
                float2 f01 = __half22float2(*reinterpret_cast<__half2*>(&raw.x));
                float2 f23 = __half22float2(*reinterpret_cast<__half2*>(&raw.y));
                a0 += ph * f01.x;
                a1 += ph * f01.y;
                a2 += ph * f23.x;
                a3 += ph * f23.y;
                ds += ph;
            }
            __syncwarp();
        }

        float inv = 1.f / (ds + 1e-8f);
        float4 av = make_float4(a0 * inv, a1 * inv, a2 * inv, a3 * inv);
        *reinterpret_cast<float4*>(&wA[lane * 4]) = av;
        __syncwarp();

        // out[col=lane] = sum_k A[k] * W[k][lane], vectorized LDS.128
        float o = 0.f;
#pragma unroll
        for (int k4 = 0; k4 < 128; k4 += 4) {
            float4 a = *reinterpret_cast<const float4*>(&wA[k4]);        // bcast
            float4 wv = *reinterpret_cast<const float4*>(&sWt[lane * 132 + k4]);
            o += a.x * wv.x + a.y * wv.y + a.z * wv.z + a.w * wv.w;
        }
        float v = o + sb[lane];
        out[(size_t)n * 32 + lane] = 0.5f * v * (1.f + erff(v * 0.70710678118f));
        __syncwarp();
    }
}

extern "C" void kernel_launch(void* const* d_in, const int* in_sizes, int n_in,
                              void* d_out, int out_size) {
    const float* NF = (const float*)d_in[0];   // node_features (N,128)
    const int*   EI = (const int*)  d_in[1];   // edge_index (E,2)
    const float* EF = (const float*)d_in[2];   // edge_features (E,32)
    const float* Wn = (const float*)d_in[3];   // W_node (128,128)
    const float* We = (const float*)d_in[4];   // W_edge (32,128)
    const float* AK = (const float*)d_in[5];   // attn_kernel (4,96)
    const float* Wo = (const float*)d_in[6];   // W_out (128,32)
    const float* bo = (const float*)d_in[7];   // b_out (32,)
    float* out = (float*)d_out;                // (N,32)

    k_prep_v<<<1, 128>>>(We, AK);
    k_zero_cnt<<<(N_NODES + 255) / 256, 256>>>();
    k_hist<<<N_EDGES / 256, 256>>>(EI);
    k_scan_blocks<<<SCAN_BLOCKS, 1024>>>();
    k_scan_part<<<1, 128>>>();
    k_scan_add<<<SCAN_BLOCKS, 1024>>>();
    k_node_gemm<<<(N_NODES + 63) / 64, 256>>>(NF, Wn, AK);
    k_permute<<<N_EDGES / 64, 256>>>(EI, EF);
    k_agg_out<<<1184, 256>>>(Wo, bo, out);
}